// round 2
// baseline (speedup 1.0000x reference)
#include <cuda_runtime.h>
#include <math.h>

#define BATCH    32768
#define DIM      256
#define MBLK     (BATCH/128)   // 256
#define NBLK     (DIM/128)     // 2
#define NCTAS    (MBLK*NBLK)   // 512
#define EW_GRID  (BATCH*DIM/4/256)  // 8192
#define MAX_IT   40

// ---------------- device scratch ----------------
__device__ float g_x[2][BATCH*DIM];   // ping-pong
__device__ float g_y[2][BATCH*DIM];   // ping-pong
__device__ float g_b[BATCH*DIM];
__device__ float g_W [DIM*DIM];       // Weff: multiply(z) = z @ Weff
__device__ float g_WU[DIM*DIM];       // U^T
__device__ float g_partial[NCTAS*2];
__device__ int   g_active;

// ---------------- packed fp32x2 helpers (sm_100+) ----------------
__device__ __forceinline__ unsigned long long pack2(float v) {
    unsigned long long r; unsigned u = __float_as_uint(v);
    asm("mov.b64 %0, {%1, %1};" : "=l"(r) : "r"(u));
    return r;
}
__device__ __forceinline__ void ffma2(unsigned long long& d,
                                      unsigned long long a,
                                      unsigned long long b) {
    asm("fma.rn.f32x2 %0, %1, %2, %0;" : "+l"(d) : "l"(a), "l"(b));
}
__device__ __forceinline__ float lo32(unsigned long long v) {
    return __uint_as_float((unsigned)(v & 0xffffffffull));
}
__device__ __forceinline__ float hi32(unsigned long long v) {
    return __uint_as_float((unsigned)(v >> 32));
}

// ---------------- prep: Weff and U^T ----------------
__global__ void prep_kernel(const float* __restrict__ U,
                            const float* __restrict__ A,
                            const float* __restrict__ B) {
    int i = blockIdx.x;    // row of Weff
    int j = threadIdx.x;   // col
    g_WU[i*DIM + j] = U[j*DIM + i];
    float s = 0.f;
#pragma unroll 8
    for (int p = 0; p < DIM; ++p)
        s = fmaf(A[p*DIM + i], A[p*DIM + j], s);
    float w = -s + B[j*DIM + i] - B[i*DIM + j];
    if (i == j) w += 0.8f;           // (1 - m), m = 0.2
    g_W[i*DIM + j] = w;
}

// ---------------- init: zero parity-0 state, arm flag ----------------
__global__ void init_kernel() {
    int i = blockIdx.x * blockDim.x + threadIdx.x;
    float4 z = make_float4(0.f, 0.f, 0.f, 0.f);
    ((float4*)g_x[0])[i] = z;
    ((float4*)g_y[0])[i] = z;
    if (i == 0) g_active = 1;
}

// ---------------- fused GEMM + FISTA step ----------------
// MODE 0:  g_b = Aop @ g_WU + ub
// MODE 1:  G = y[par] @ g_W  (regs only); then per element:
//          fn   = relu(G + b)               -> outp (candidate final output)
//          err partials from (y, fn)
//          xnew = relu(0.5*(y + G + b))     -> g_x[par^1]
//          ynew = xnew + beta*(xnew - x)    -> g_y[par^1]
template<int MODE>
__launch_bounds__(256, 2)
__global__ void gemm_kernel(const float* __restrict__ Aop,
                            const float* __restrict__ ub,
                            float beta, int par,
                            float* __restrict__ outp) {
    if (MODE == 1 && g_active == 0) return;

    __shared__ float As[2][16][132];   // [buf][k][m]
    __shared__ float Bs[2][16][128];   // [buf][k][n]

    const float* __restrict__ Ap = (MODE == 0) ? Aop  : g_y[par];
    const float* __restrict__ Bp = (MODE == 0) ? g_WU : g_W;

    const int tid = threadIdx.x;
    const int tx  = tid & 15;          // n pair index
    const int ty  = tid >> 4;          // m group of 8
    const int m0  = blockIdx.y * 128;
    const int n0  = blockIdx.x * 128;

    const int ra = tid >> 2;           // 0..63
    const int ca = (tid & 3) << 2;     // 0,4,8,12
    const int rb = tid >> 5;           // 0..7
    const int cb = (tid & 31) << 2;    // 0..124

    unsigned long long acc[8][4];
#pragma unroll
    for (int i = 0; i < 8; ++i)
#pragma unroll
        for (int j = 0; j < 4; ++j) acc[i][j] = 0ull;

    const float* aptr0 = Ap + (m0 + ra) * DIM + ca;
    const float* aptr1 = aptr0 + 64 * DIM;
    const float* bptr0 = Bp + rb * DIM + n0 + cb;
    const float* bptr1 = bptr0 + 8 * DIM;

    // prologue: tile 0 -> buffer 0
    float4 a0 = *(const float4*)aptr0;
    float4 a1 = *(const float4*)aptr1;
    float4 b0 = *(const float4*)bptr0;
    float4 b1 = *(const float4*)bptr1;
    As[0][ca+0][ra] = a0.x;  As[0][ca+1][ra] = a0.y;
    As[0][ca+2][ra] = a0.z;  As[0][ca+3][ra] = a0.w;
    As[0][ca+0][ra+64] = a1.x;  As[0][ca+1][ra+64] = a1.y;
    As[0][ca+2][ra+64] = a1.z;  As[0][ca+3][ra+64] = a1.w;
    *(float4*)&Bs[0][rb  ][cb] = b0;
    *(float4*)&Bs[0][rb+8][cb] = b1;
    __syncthreads();

    for (int t = 0; t < 16; ++t) {
        // issue next tile's global loads before compute
        if (t < 15) {
            a0 = *(const float4*)(aptr0 + (t + 1) * 16);
            a1 = *(const float4*)(aptr1 + (t + 1) * 16);
            b0 = *(const float4*)(bptr0 + (t + 1) * 16 * DIM);
            b1 = *(const float4*)(bptr1 + (t + 1) * 16 * DIM);
        }
        float (*Ar)[132] = As[t & 1];
        float (*Br)[128] = Bs[t & 1];
#pragma unroll
        for (int kk = 0; kk < 16; ++kk) {
            unsigned long long pb[4], pa[8];
#pragma unroll
            for (int j = 0; j < 4; ++j)
                pb[j] = *(const unsigned long long*)&Br[kk][tx*2 + j*32];
#pragma unroll
            for (int i = 0; i < 8; ++i)
                pa[i] = pack2(Ar[kk][ty*8 + i]);
#pragma unroll
            for (int i = 0; i < 8; ++i)
#pragma unroll
                for (int j = 0; j < 4; ++j)
                    ffma2(acc[i][j], pa[i], pb[j]);
        }
        if (t < 15) {
            float (*Aw)[132] = As[(t + 1) & 1];
            float (*Bw)[128] = Bs[(t + 1) & 1];
            Aw[ca+0][ra] = a0.x;  Aw[ca+1][ra] = a0.y;
            Aw[ca+2][ra] = a0.z;  Aw[ca+3][ra] = a0.w;
            Aw[ca+0][ra+64] = a1.x;  Aw[ca+1][ra+64] = a1.y;
            Aw[ca+2][ra+64] = a1.z;  Aw[ca+3][ra+64] = a1.w;
            *(float4*)&Bw[rb  ][cb] = b0;
            *(float4*)&Bw[rb+8][cb] = b1;
            __syncthreads();
        }
    }

    if (MODE == 0) {
        float2 u[4];
#pragma unroll
        for (int j = 0; j < 4; ++j)
            u[j] = *(const float2*)(ub + n0 + tx*2 + j*32);
#pragma unroll
        for (int i = 0; i < 8; ++i) {
            int m = m0 + ty*8 + i;
            float* base = g_b + m*DIM + n0;
#pragma unroll
            for (int j = 0; j < 4; ++j) {
                float2 g;
                g.x = lo32(acc[i][j]) + u[j].x;
                g.y = hi32(acc[i][j]) + u[j].y;
                *(float2*)(base + tx*2 + j*32) = g;
            }
        }
    } else {
        const float* __restrict__ yr = g_y[par];
        const float* __restrict__ xr = g_x[par];
        float* __restrict__ yw = g_y[par ^ 1];
        float* __restrict__ xw = g_x[par ^ 1];
        float sn = 0.f, sd = 0.f;
#pragma unroll
        for (int i = 0; i < 8; ++i) {
            int m = m0 + ty*8 + i;
            const float* brow = g_b + m*DIM + n0;
            const float* yrow = yr  + m*DIM + n0;
            const float* xrow = xr  + m*DIM + n0;
            float* orow  = outp + m*DIM + n0;
            float* xwrow = xw   + m*DIM + n0;
            float* ywrow = yw   + m*DIM + n0;
#pragma unroll
            for (int j = 0; j < 4; ++j) {
                int c = tx*2 + j*32;
                float2 bv = *(const float2*)(brow + c);
                float2 yv = *(const float2*)(yrow + c);
                float2 xv = *(const float2*)(xrow + c);
                float2 g;
                g.x = lo32(acc[i][j]);
                g.y = hi32(acc[i][j]);
                // residual check (belongs to previous reference body)
                float2 fn;
                fn.x = fmaxf(g.x + bv.x, 0.f);
                fn.y = fmaxf(g.y + bv.y, 0.f);
                float d0 = yv.x - fn.x, d1 = yv.y - fn.y;
                sn = fmaf(d0, d0, sn);  sn = fmaf(d1, d1, sn);
                sd = fmaf(yv.x, yv.x, sd);  sd = fmaf(yv.y, yv.y, sd);
                *(float2*)(orow + c) = fn;          // candidate final output
                // forward FISTA step
                float2 xn, yn;
                xn.x = fmaxf(0.5f*(yv.x + g.x + bv.x), 0.f);
                xn.y = fmaxf(0.5f*(yv.y + g.y + bv.y), 0.f);
                yn.x = xn.x + beta*(xn.x - xv.x);
                yn.y = xn.y + beta*(xn.y - xv.y);
                *(float2*)(xwrow + c) = xn;
                *(float2*)(ywrow + c) = yn;
            }
        }
        // deterministic block reduction (no atomics -> bit-stable err)
        __syncthreads();
        float* red = &As[0][0][0];   // scratch; need 512 floats
        red[tid]       = sn;
        red[256 + tid] = sd;
        __syncthreads();
#pragma unroll
        for (int s = 128; s > 0; s >>= 1) {
            if (tid < s) {
                red[tid]       += red[tid + s];
                red[256 + tid] += red[256 + tid + s];
            }
            __syncthreads();
        }
        if (tid == 0) {
            int bid = blockIdx.y * NBLK + blockIdx.x;
            g_partial[bid*2    ] = red[0];
            g_partial[bid*2 + 1] = red[256];
        }
    }
}

// ---------------- convergence check ----------------
__global__ void check_kernel() {
    if (g_active == 0) return;
    __shared__ float sn[256], sd[256];
    int t = threadIdx.x;
    float a = g_partial[2*t      ] + g_partial[2*(t + 256)    ];
    float b = g_partial[2*t + 1  ] + g_partial[2*(t + 256) + 1];
    sn[t] = a; sd[t] = b;
    __syncthreads();
#pragma unroll
    for (int s = 128; s > 0; s >>= 1) {
        if (t < s) { sn[t] += sn[t + s]; sd[t] += sd[t + s]; }
        __syncthreads();
    }
    if (t == 0) {
        float err = sqrtf(sn[0]) / (1e-6f + sqrtf(sd[0]));
        if (!(err > 1e-4f)) g_active = 0;
    }
}

// ---------------- launch ----------------
extern "C" void kernel_launch(void* const* d_in, const int* in_sizes, int n_in,
                              void* d_out, int out_size) {
    const float* x  = (const float*)d_in[0];
    const float* U  = (const float*)d_in[1];
    const float* ub = (const float*)d_in[2];
    const float* A  = (const float*)d_in[3];
    const float* B  = (const float*)d_in[4];
    (void)in_sizes; (void)n_in; (void)out_size;

    prep_kernel<<<DIM, DIM>>>(U, A, B);
    init_kernel<<<EW_GRID, 256>>>();

    dim3 ggrid(NBLK, MBLK);
    gemm_kernel<0><<<ggrid, 256>>>(x, ub, 0.f, 0, nullptr);   // b = x@U^T + ub

    // Fused kernel i (i=1..41): forward of reference body i + err/fn of body i-1.
    // Check after kernel i gates kernel i+1 on err_{i-1} (exact reference gating:
    // body i+1 runs iff err_i > TOL; our extra forward in the kernel that detects
    // convergence never reaches d_out).
    float t = 1.0f;
    for (int i = 1; i <= MAX_IT + 1; ++i) {
        float tn   = 0.5f * (1.0f + sqrtf(1.0f + 4.0f * t * t));
        float beta = (t - 1.0f) / tn;
        gemm_kernel<1><<<ggrid, 256>>>(nullptr, nullptr, beta, (i - 1) & 1,
                                       (float*)d_out);
        if (i <= MAX_IT) check_kernel<<<1, 256>>>();
        t = tn;
    }
}

// round 5
// speedup vs baseline: 1.5588x; 1.5588x over previous
#include <cuda_runtime.h>
#include <cuda_bf16.h>
#include <math.h>
#include <stdint.h>

#define BATCH    32768
#define DIM      256
#define MAX_IT   40
#define NCTAS    512               // (BATCH/128) * (DIM/128)
#define EW_GRID  (BATCH*DIM/4/256)

// ---------------- device scratch ----------------
__device__ float g_x[2][BATCH*DIM];
__device__ float g_y[2][BATCH*DIM];
__device__ float g_b[BATCH*DIM];
__device__ float g_WU[DIM*DIM];               // U^T for bias GEMM
__device__ __nv_bfloat16 g_w0[DIM*DIM];       // Weff hi split, [k][n] row-major
__device__ __nv_bfloat16 g_w1[DIM*DIM];       // Weff lo split
__device__ float g_partial[NCTAS*2];
__device__ int   g_active;

// ---------------- helpers ----------------
__device__ __forceinline__ uint32_t sptr(const void* p) {
    return (uint32_t)__cvta_generic_to_shared(p);
}
__device__ __forceinline__ uint32_t bpack(__nv_bfloat16 a, __nv_bfloat16 b) {
    uint16_t ua = *(uint16_t*)&a, ub = *(uint16_t*)&b;
    return (uint32_t)ua | ((uint32_t)ub << 16);
}
__device__ __forceinline__ void ldm_x4(uint32_t* r, uint32_t addr) {
    asm volatile("ldmatrix.sync.aligned.m8n8.x4.shared.b16 {%0,%1,%2,%3}, [%4];"
                 : "=r"(r[0]), "=r"(r[1]), "=r"(r[2]), "=r"(r[3]) : "r"(addr));
}
__device__ __forceinline__ void ldm_x4t(uint32_t* r, uint32_t addr) {
    asm volatile("ldmatrix.sync.aligned.m8n8.x4.trans.shared.b16 {%0,%1,%2,%3}, [%4];"
                 : "=r"(r[0]), "=r"(r[1]), "=r"(r[2]), "=r"(r[3]) : "r"(addr));
}
__device__ __forceinline__ void mma_bf16(float* c, const uint32_t* a, const uint32_t* b) {
    asm volatile(
        "mma.sync.aligned.m16n8k16.row.col.f32.bf16.bf16.f32 "
        "{%0,%1,%2,%3}, {%4,%5,%6,%7}, {%8,%9}, {%0,%1,%2,%3};"
        : "+f"(c[0]), "+f"(c[1]), "+f"(c[2]), "+f"(c[3])
        : "r"(a[0]), "r"(a[1]), "r"(a[2]), "r"(a[3]), "r"(b[0]), "r"(b[1]));
}

// fp32x2 helpers for the bias GEMM
__device__ __forceinline__ unsigned long long pack2(float v) {
    unsigned long long r; unsigned u = __float_as_uint(v);
    asm("mov.b64 %0, {%1, %1};" : "=l"(r) : "r"(u));
    return r;
}
__device__ __forceinline__ void ffma2(unsigned long long& d,
                                      unsigned long long a, unsigned long long b) {
    asm("fma.rn.f32x2 %0, %1, %2, %0;" : "+l"(d) : "l"(a), "l"(b));
}
__device__ __forceinline__ float lo32(unsigned long long v) {
    return __uint_as_float((unsigned)(v & 0xffffffffull));
}
__device__ __forceinline__ float hi32(unsigned long long v) {
    return __uint_as_float((unsigned)(v >> 32));
}

// ---------------- prep: U^T, Weff -> bf16 splits ----------------
__global__ void prep_kernel(const float* __restrict__ U,
                            const float* __restrict__ A,
                            const float* __restrict__ B) {
    int i = blockIdx.x;    // k index (row of Weff)
    int j = threadIdx.x;   // n index (col)
    g_WU[i*DIM + j] = U[j*DIM + i];
    float s = 0.f;
#pragma unroll 8
    for (int p = 0; p < DIM; ++p)
        s = fmaf(A[p*DIM + i], A[p*DIM + j], s);
    float w = -s + B[j*DIM + i] - B[i*DIM + j];
    if (i == j) w += 0.8f;                    // (1-m), m=0.2
    __nv_bfloat16 h0 = __float2bfloat16(w);
    __nv_bfloat16 h1 = __float2bfloat16(w - __bfloat162float(h0));
    g_w0[i*DIM + j] = h0;
    g_w1[i*DIM + j] = h1;
}

__global__ void init_kernel() {
    int i = blockIdx.x * blockDim.x + threadIdx.x;
    float4 z = make_float4(0.f, 0.f, 0.f, 0.f);
    ((float4*)g_x[0])[i] = z;
    ((float4*)g_y[0])[i] = z;
    if (i == 0) g_active = 1;
}

// ---------------- bias GEMM (runs once, exact fp32): b = x @ U^T + ub ----------
__launch_bounds__(256, 2)
__global__ void bias_gemm(const float* __restrict__ Ap, const float* __restrict__ ub) {
    __shared__ float As[16][132];
    __shared__ float Bs[16][128];
    const int tid = threadIdx.x;
    const int tx  = tid & 15, ty = tid >> 4;
    const int m0  = blockIdx.y * 128, n0 = blockIdx.x * 128;
    const int ra = tid >> 2, ca = (tid & 3) << 2;
    const int rb = tid >> 5, cb = (tid & 31) << 2;
    unsigned long long acc[8][4];
#pragma unroll
    for (int i = 0; i < 8; ++i)
#pragma unroll
        for (int j = 0; j < 4; ++j) acc[i][j] = 0ull;
    for (int k0 = 0; k0 < DIM; k0 += 16) {
        float4 a0 = *(const float4*)(Ap + (m0 + ra     ) * DIM + k0 + ca);
        float4 a1 = *(const float4*)(Ap + (m0 + ra + 64) * DIM + k0 + ca);
        float4 b0 = *(const float4*)(g_WU + (k0 + rb    ) * DIM + n0 + cb);
        float4 b1 = *(const float4*)(g_WU + (k0 + rb + 8) * DIM + n0 + cb);
        __syncthreads();
        As[ca+0][ra] = a0.x;  As[ca+1][ra] = a0.y;
        As[ca+2][ra] = a0.z;  As[ca+3][ra] = a0.w;
        As[ca+0][ra+64] = a1.x;  As[ca+1][ra+64] = a1.y;
        As[ca+2][ra+64] = a1.z;  As[ca+3][ra+64] = a1.w;
        *(float4*)&Bs[rb  ][cb] = b0;
        *(float4*)&Bs[rb+8][cb] = b1;
        __syncthreads();
#pragma unroll
        for (int kk = 0; kk < 16; ++kk) {
            unsigned long long pb[4], pa[8];
#pragma unroll
            for (int j = 0; j < 4; ++j)
                pb[j] = *(const unsigned long long*)&Bs[kk][tx*2 + j*32];
#pragma unroll
            for (int i = 0; i < 8; ++i) pa[i] = pack2(As[kk][ty*8 + i]);
#pragma unroll
            for (int i = 0; i < 8; ++i)
#pragma unroll
                for (int j = 0; j < 4; ++j) ffma2(acc[i][j], pa[i], pb[j]);
        }
    }
    float2 u[4];
#pragma unroll
    for (int j = 0; j < 4; ++j) u[j] = *(const float2*)(ub + n0 + tx*2 + j*32);
#pragma unroll
    for (int i = 0; i < 8; ++i) {
        float* base = g_b + (m0 + ty*8 + i)*DIM + n0;
#pragma unroll
        for (int j = 0; j < 4; ++j) {
            float2 g;
            g.x = lo32(acc[i][j]) + u[j].x;
            g.y = hi32(acc[i][j]) + u[j].y;
            *(float2*)(base + tx*2 + j*32) = g;
        }
    }
}

// ---------------- iteration kernel: mma.sync split-bf16 GEMM + fused FISTA ----
// G[128,128] = a0@w0 + a1@w0 + a0@w1 (fp32 accum), then per element:
//   fn = relu(G+b) -> out; err partials from (y, fn);
//   x' = relu(0.5*(y+G+b)) -> g_x[par^1]; y' = x' + beta*(x'-x) -> g_y[par^1]
__global__ void __launch_bounds__(256, 2)
iter_kernel(float beta, int par, float* __restrict__ outp) {
    if (g_active == 0) return;
    __shared__ __nv_bfloat16 A0s[128][40];   // pad 40: conflict-free ldmatrix
    __shared__ __nv_bfloat16 A1s[128][40];
    __shared__ __nv_bfloat16 W0s[32][136];   // pad 136
    __shared__ __nv_bfloat16 W1s[32][136];

    const int tid  = threadIdx.x;
    const int lane = tid & 31;
    const int wid  = tid >> 5;
    const int wm   = wid & 3;      // warp M index (32 rows each)
    const int wn   = wid >> 2;     // warp N index (64 cols each)
    const int m0   = blockIdx.y * 128;
    const int n0   = blockIdx.x * 128;

    const float* __restrict__ yr = g_y[par];

    float acc[2][8][4];
#pragma unroll
    for (int mi = 0; mi < 2; ++mi)
#pragma unroll
        for (int ni = 0; ni < 8; ++ni)
#pragma unroll
            for (int q = 0; q < 4; ++q) acc[mi][ni][q] = 0.f;

    // ldmatrix lane addresses
    // A: lanes 0-15 -> rows m_base+lane @ col kk; 16-31 -> same rows @ kk+8
    const uint32_t aoff = (uint32_t)(((wm*32 + (lane & 15)) * 40 + (lane >> 4) * 8) * 2);
    const uint32_t a0addr = sptr(A0s) + aoff;
    const uint32_t a1addr = sptr(A1s) + aoff;
    // B (trans): matrices (k0-7,n0-7)(k8-15,n0-7)(k0-7,n8-15)(k8-15,n8-15)
    const uint32_t boff = (uint32_t)(((((lane >> 3) & 1) * 8 + (lane & 7)) * 136
                                      + wn*64 + (lane >> 4) * 8) * 2);
    const uint32_t w0addr = sptr(W0s) + boff;
    const uint32_t w1addr = sptr(W1s) + boff;

    for (int kc = 0; kc < 8; ++kc) {
        // --- y tile -> bf16 splits into smem ---
#pragma unroll
        for (int p = 0; p < 4; ++p) {
            int idx = tid + p * 256;
            int row = idx >> 3, c4 = (idx & 7) << 2;
            float4 v = *(const float4*)(yr + (m0 + row) * DIM + kc * 32 + c4);
            __nv_bfloat16 h0 = __float2bfloat16(v.x);
            __nv_bfloat16 h1 = __float2bfloat16(v.y);
            __nv_bfloat16 h2 = __float2bfloat16(v.z);
            __nv_bfloat16 h3 = __float2bfloat16(v.w);
            __nv_bfloat16 l0 = __float2bfloat16(v.x - __bfloat162float(h0));
            __nv_bfloat16 l1 = __float2bfloat16(v.y - __bfloat162float(h1));
            __nv_bfloat16 l2 = __float2bfloat16(v.z - __bfloat162float(h2));
            __nv_bfloat16 l3 = __float2bfloat16(v.w - __bfloat162float(h3));
            *(uint2*)&A0s[row][c4] = make_uint2(bpack(h0, h1), bpack(h2, h3));
            *(uint2*)&A1s[row][c4] = make_uint2(bpack(l0, l1), bpack(l2, l3));
        }
        // --- W chunk [32][128] per split ---
#pragma unroll
        for (int p = 0; p < 2; ++p) {
            int idx = tid + p * 256;
            int kr = idx >> 4, nc = (idx & 15) << 3;
            *(uint4*)&W0s[kr][nc] =
                *(const uint4*)(g_w0 + (kc*32 + kr) * DIM + n0 + nc);
            *(uint4*)&W1s[kr][nc] =
                *(const uint4*)(g_w1 + (kc*32 + kr) * DIM + n0 + nc);
        }
        __syncthreads();

#pragma unroll
        for (int kk2 = 0; kk2 < 2; ++kk2) {
            const uint32_t akb = (uint32_t)(kk2 * 16 * 2);       // col offset bytes
            const uint32_t bkb = (uint32_t)(kk2 * 16 * 136 * 2); // row offset bytes
            uint32_t a0f[2][4], a1f[2][4];
            ldm_x4(a0f[0], a0addr + akb);
            ldm_x4(a0f[1], a0addr + akb + 16*40*2);
            ldm_x4(a1f[0], a1addr + akb);
            ldm_x4(a1f[1], a1addr + akb + 16*40*2);
            uint32_t bf[8][2];
#pragma unroll
            for (int nb = 0; nb < 4; ++nb) {
                uint32_t r[4];
                ldm_x4t(r, w0addr + bkb + nb*16*2);
                bf[nb*2  ][0] = r[0];  bf[nb*2  ][1] = r[1];
                bf[nb*2+1][0] = r[2];  bf[nb*2+1][1] = r[3];
            }
#pragma unroll
            for (int mi = 0; mi < 2; ++mi)
#pragma unroll
                for (int ni = 0; ni < 8; ++ni)
                    mma_bf16(acc[mi][ni], a0f[mi], bf[ni]);
#pragma unroll
            for (int mi = 0; mi < 2; ++mi)
#pragma unroll
                for (int ni = 0; ni < 8; ++ni)
                    mma_bf16(acc[mi][ni], a1f[mi], bf[ni]);
#pragma unroll
            for (int nb = 0; nb < 4; ++nb) {
                uint32_t r[4];
                ldm_x4t(r, w1addr + bkb + nb*16*2);
                bf[nb*2  ][0] = r[0];  bf[nb*2  ][1] = r[1];
                bf[nb*2+1][0] = r[2];  bf[nb*2+1][1] = r[3];
            }
#pragma unroll
            for (int mi = 0; mi < 2; ++mi)
#pragma unroll
                for (int ni = 0; ni < 8; ++ni)
                    mma_bf16(acc[mi][ni], a0f[mi], bf[ni]);
        }
        __syncthreads();
    }

    // --- fused epilogue at fragment positions (float2 = full 32B sectors) ---
    const float* __restrict__ xr = g_x[par];
    float* __restrict__ xw = g_x[par ^ 1];
    float* __restrict__ yw = g_y[par ^ 1];
    float sn = 0.f, sd = 0.f;
#pragma unroll
    for (int mi = 0; mi < 2; ++mi) {
#pragma unroll
        for (int h = 0; h < 2; ++h) {
            int row = m0 + wm*32 + mi*16 + (lane >> 2) + h*8;
#pragma unroll
            for (int ni = 0; ni < 8; ++ni) {
                int col = n0 + wn*64 + ni*8 + (lane & 3)*2;
                int gi = row * DIM + col;
                float g0 = acc[mi][ni][h*2], g1 = acc[mi][ni][h*2 + 1];
                float2 bv = *(const float2*)(g_b + gi);
                float2 yv = *(const float2*)(yr + gi);
                float2 xv = *(const float2*)(xr + gi);
                float2 fn, xn, yn;
                fn.x = fmaxf(g0 + bv.x, 0.f);
                fn.y = fmaxf(g1 + bv.y, 0.f);
                float d0 = yv.x - fn.x, d1 = yv.y - fn.y;
                sn = fmaf(d0, d0, sn);      sn = fmaf(d1, d1, sn);
                sd = fmaf(yv.x, yv.x, sd);  sd = fmaf(yv.y, yv.y, sd);
                xn.x = fmaxf(0.5f*(yv.x + g0 + bv.x), 0.f);
                xn.y = fmaxf(0.5f*(yv.y + g1 + bv.y), 0.f);
                yn.x = xn.x + beta*(xn.x - xv.x);
                yn.y = xn.y + beta*(xn.y - xv.y);
                *(float2*)(outp + gi) = fn;
                *(float2*)(xw + gi)   = xn;
                *(float2*)(yw + gi)   = yn;
            }
        }
    }

    // deterministic block reduction
    __syncthreads();
    float* red = (float*)&A0s[0][0];
    red[tid] = sn;  red[256 + tid] = sd;
    __syncthreads();
#pragma unroll
    for (int s = 128; s > 0; s >>= 1) {
        if (tid < s) { red[tid] += red[tid + s]; red[256 + tid] += red[256 + tid + s]; }
        __syncthreads();
    }
    if (tid == 0) {
        int bid = blockIdx.y * 2 + blockIdx.x;
        g_partial[bid*2    ] = red[0];
        g_partial[bid*2 + 1] = red[256];
    }
}

// ---------------- convergence check ----------------
__global__ void check_kernel() {
    if (g_active == 0) return;
    __shared__ float sn[256], sd[256];
    int t = threadIdx.x;
    float a = g_partial[2*t      ] + g_partial[2*(t + 256)    ];
    float b = g_partial[2*t + 1  ] + g_partial[2*(t + 256) + 1];
    sn[t] = a; sd[t] = b;
    __syncthreads();
#pragma unroll
    for (int s = 128; s > 0; s >>= 1) {
        if (t < s) { sn[t] += sn[t + s]; sd[t] += sd[t + s]; }
        __syncthreads();
    }
    if (t == 0) {
        float err = sqrtf(sn[0]) / (1e-6f + sqrtf(sd[0]));
        if (!(err > 1e-4f)) g_active = 0;
    }
}

// ---------------- launch ----------------
extern "C" void kernel_launch(void* const* d_in, const int* in_sizes, int n_in,
                              void* d_out, int out_size) {
    const float* x  = (const float*)d_in[0];
    const float* U  = (const float*)d_in[1];
    const float* ub = (const float*)d_in[2];
    const float* A  = (const float*)d_in[3];
    const float* B  = (const float*)d_in[4];
    (void)in_sizes; (void)n_in; (void)out_size;

    prep_kernel<<<DIM, DIM>>>(U, A, B);
    init_kernel<<<EW_GRID, 256>>>();

    dim3 bgrid(2, 256);
    bias_gemm<<<bgrid, 256>>>(x, ub);

    // kernel i: forward of body i + fn/err of body i-1 (gating validated R1/R2)
    dim3 igrid(2, 256);
    float t = 1.0f;
    for (int i = 1; i <= MAX_IT + 1; ++i) {
        float tn   = 0.5f * (1.0f + sqrtf(1.0f + 4.0f * t * t));
        float beta = (t - 1.0f) / tn;
        iter_kernel<<<igrid, 256>>>(beta, (i - 1) & 1, (float*)d_out);
        if (i <= MAX_IT) check_kernel<<<1, 256>>>();
        t = tn;
    }
}